// round 9
// baseline (speedup 1.0000x reference)
#include <cuda_runtime.h>

// Problem constants (fixed shapes for this problem)
#define NEDGE 160000

// Scratch (static device arrays — cudaMalloc is forbidden)
__device__ __align__(16) float g_T[972];   // T[(a*9+b)*12 + d], pad 12

typedef unsigned long long u64;

// ---------------------------------------------------------------------------
// packed f32x2 helpers (Blackwell FFMA2)
// ---------------------------------------------------------------------------
__device__ __forceinline__ u64 pk2(float x, float y) {
    u64 r; asm("mov.b64 %0, {%1, %2};" : "=l"(r) : "f"(x), "f"(y)); return r;
}
__device__ __forceinline__ void up2(u64 v, float& x, float& y) {
    asm("mov.b64 {%0, %1}, %2;" : "=f"(x), "=f"(y) : "l"(v));
}
__device__ __forceinline__ u64 ffma2(u64 a, u64 b, u64 c) {
    u64 d; asm("fma.rn.f32x2 %0, %1, %2, %3;" : "=l"(d) : "l"(a), "l"(b), "l"(c));
    return d;
}

__device__ __forceinline__ float sspf(float x) {
    float e = __expf(-fabsf(x));
    return fmaxf(x, 0.0f) + __logf(1.0f + e) - 0.69314718055994531f;
}

// ---------------------------------------------------------------------------
// gridval: real 9x9 grid value of one spherical basis vector through
// pad -> ifftshift -> truncate -> irfft2 (numpy Im(DC)-dropped convention)
// ---------------------------------------------------------------------------
__device__ __forceinline__ float gridval(const float* __restrict__ Ur,
                                         const float* __restrict__ Ui,
                                         int a, int s, int t,
                                         const float* C, const float* S) {
    float acc = 0.0f;
    #pragma unroll
    for (int v = 0; v < 5; v++) {
        float gr = 0.0f, gi = 0.0f;
        int jj = (v + 4) % 9 - 2;                 // padded col -> U col
        if (jj >= 0 && jj < 5) {
            #pragma unroll
            for (int u = 0; u < 9; u++) {
                int ii = (u + 4) % 9 - 2;         // padded row -> U row
                if (ii >= 0 && ii < 5) {
                    float cr = Ur[a * 25 + ii * 5 + jj];
                    float ci = Ui[a * 25 + ii * 5 + jj];
                    int k = (u * s) % 9;
                    gr += cr * C[k] - ci * S[k];
                    gi += cr * S[k] + ci * C[k];
                }
            }
        }
        if (v == 0) {
            acc += gr;                             // Im(DC) dropped
        } else {
            int k2 = (v * t) % 9;
            acc += 2.0f * (gr * C[k2] - gi * S[k2]);
        }
    }
    return acc * (1.0f / 81.0f);
}

// ---------------------------------------------------------------------------
// kprep: all blocks zero the output; block 0 additionally builds T.
// ---------------------------------------------------------------------------
__global__ void __launch_bounds__(256) kprep(
    const float* __restrict__ Uxr, const float* __restrict__ Uxi,
    const float* __restrict__ Ufr, const float* __restrict__ Ufi,
    const float* __restrict__ Vr,  const float* __restrict__ Vi,
    const float* __restrict__ denom,
    float4* __restrict__ o4, int n4) {
    __shared__ float C9[9], S9[9];
    __shared__ float Gx[729], Gf[729], Pm[729];

    int tid = threadIdx.x;
    int i = blockIdx.x * 256 + tid;
    if (i < n4) o4[i] = make_float4(0.f, 0.f, 0.f, 0.f);

    if (blockIdx.x != 0) return;

    if (tid < 9) {
        double ang = 2.0 * 3.14159265358979323846 * (double)tid / 9.0;
        C9[tid] = (float)cos(ang);
        S9[tid] = (float)sin(ang);
    }
    __syncthreads();
    for (int idx = tid; idx < 729; idx += 256) {
        {   // grid bases: idx = a*81 + s*9 + t
            int a = idx / 81, s = (idx / 9) % 9, t = idx % 9;
            Gx[idx] = gridval(Uxr, Uxi, a, s, t, C9, S9);
            Gf[idx] = gridval(Ufr, Ufi, a, s, t, C9, S9);
        }
        {   // projection: idx = (s*9+t)*9 + d
            int st = idx / 9, d = idx % 9;
            int s = st / 9, t = st % 9;
            float p = 0.0f;
            #pragma unroll
            for (int u = 0; u < 9; u++)
                #pragma unroll
                for (int k = 0; k < 5; k++) {
                    int th = (u * s + k * t) % 9;
                    p += Vr[u * 45 + k * 9 + d] * C9[th]
                       + Vi[u * 45 + k * 9 + d] * S9[th];
                }
            Pm[idx] = p;
        }
    }
    __syncthreads();
    float inv = 1.0f / denom[0];
    for (int idx = tid; idx < 729; idx += 256) {
        int a = idx / 81, b = (idx / 9) % 9, d = idx % 9;
        float acc = 0.0f;
        #pragma unroll 9
        for (int st = 0; st < 81; st++)
            acc += Gx[a * 81 + st] * Gf[b * 81 + st] * Pm[st * 9 + d];
        g_T[(a * 9 + b) * 12 + d] = acc * inv;
    }
}

// ---------------------------------------------------------------------------
// kedge: fused MLP + message + scatter. 128 threads = 64 edges/block,
// 2 threads per edge (hf = half index).
//   MLP: each thread computes its kq-half of layers 1/2 (acc[16]) and its
//        q-half of layer 3; partners exchange 32 activations per layer
//        boundary via shfl.xor(1). Layer-3 half output wf[24] == the weights
//        for this thread's two message chunks.
//   Message: R7 per-chunk compute + aligned cooperative atomic flush.
//   fbuf aliases the dead W1+W2 smem after a block barrier.
// ---------------------------------------------------------------------------
__global__ void __launch_bounds__(128, 3) kedge(
    const float* __restrict__ win,
    const float* __restrict__ fsph,
    const int*   __restrict__ eidx,
    const float* __restrict__ W1,
    const float* __restrict__ W2,
    const float* __restrict__ W3,
    const float* __restrict__ aw,
    const float* __restrict__ x,
    float* __restrict__ out,
    int E) {
    __shared__ __align__(16) float pool[7680];   // w1(512)+w2(4096)+w3(3072)
    __shared__ __align__(16) float Tsh[972];
    __shared__ float awsh[27];
    // fbuf aliases pool[0..4608) after the mid-kernel barrier (w1,w2 dead)

    float4* w1s = (float4*)pool;            // 8x64
    float4* w2s = (float4*)(pool + 512);    // 64x64
    float4* w3s = (float4*)(pool + 4608);   // 64x48

    int tid  = threadIdx.x;
    int wid  = tid >> 5;
    int lane = tid & 31;
    int hf   = tid & 1;          // half index within edge pair

    // ---- stage weights / T / aw ----
    const float4* W1v = (const float4*)W1;
    const float4* W2v = (const float4*)W2;
    const float4* W3v = (const float4*)W3;
    w1s[tid] = W1v[tid];
    #pragma unroll
    for (int i = 0; i < 8; i++) w2s[tid + i * 128] = W2v[tid + i * 128];
    #pragma unroll
    for (int i = 0; i < 6; i++) w3s[tid + i * 128] = W3v[tid + i * 128];
    #pragma unroll
    for (int i = 0; i < 8; i++) {
        int idx = tid + i * 128;
        if (idx < 972) Tsh[idx] = g_T[idx];
    }
    if (tid < 27) awsh[tid] = aw[tid];
    __syncthreads();

    int e = blockIdx.x * 64 + (tid >> 1);
    int valid = (e < E) ? 1 : 0;
    int ec = valid ? e : 0;
    int dst = __ldg(&eidx[ec]);
    int src = __ldg(&eidx[E + ec]);

    const ulonglong2* w1p = (const ulonglong2*)w1s;
    const ulonglong2* w2p = (const ulonglong2*)w2s;
    const ulonglong2* w3p = (const ulonglong2*)w3s;

    float4 wa = __ldg(&((const float4*)win)[(size_t)ec * 2 + 0]);
    float4 wb = __ldg(&((const float4*)win)[(size_t)ec * 2 + 1]);
    float wi[8] = {wa.x, wa.y, wa.z, wa.w, wb.x, wb.y, wb.z, wb.w};

    u64 acc[16];
    float h[64];

    // ----- layer 1 (kq-half) -----
    #pragma unroll
    for (int t = 0; t < 16; t++) acc[t] = 0ull;
    #pragma unroll
    for (int i = 0; i < 8; i++) {
        u64 hi = pk2(wi[i], wi[i]);
        #pragma unroll
        for (int k8 = 0; k8 < 8; k8++) {
            ulonglong2 wp = w1p[i * 16 + hf * 8 + k8];
            acc[2 * k8 + 0] = ffma2(hi, wp.x, acc[2 * k8 + 0]);
            acc[2 * k8 + 1] = ffma2(hi, wp.y, acc[2 * k8 + 1]);
        }
    }
    {
        const float s1 = 0.35355339059327373f;
        float hown[32];
        #pragma unroll
        for (int t = 0; t < 16; t++) {
            float v0, v1; up2(acc[t], v0, v1);
            hown[2 * t + 0] = sspf(v0 * s1);
            hown[2 * t + 1] = sspf(v1 * s1);
        }
        #pragma unroll
        for (int jl = 0; jl < 32; jl++) {
            float mine = hown[jl];
            float theirs = __shfl_xor_sync(0xffffffffu, mine, 1);
            h[jl]      = hf ? theirs : mine;
            h[32 + jl] = hf ? mine   : theirs;
        }
    }

    // ----- layer 2 (kq-half) -----
    #pragma unroll
    for (int t = 0; t < 16; t++) acc[t] = 0ull;
    #pragma unroll 4
    for (int j = 0; j < 64; j++) {
        u64 hj = pk2(h[j], h[j]);
        #pragma unroll
        for (int k8 = 0; k8 < 8; k8++) {
            ulonglong2 wp = w2p[j * 16 + hf * 8 + k8];
            acc[2 * k8 + 0] = ffma2(hj, wp.x, acc[2 * k8 + 0]);
            acc[2 * k8 + 1] = ffma2(hj, wp.y, acc[2 * k8 + 1]);
        }
    }
    {
        float hown[32];
        #pragma unroll
        for (int t = 0; t < 16; t++) {
            float v0, v1; up2(acc[t], v0, v1);
            hown[2 * t + 0] = sspf(v0 * 0.125f);
            hown[2 * t + 1] = sspf(v1 * 0.125f);
        }
        #pragma unroll
        for (int jl = 0; jl < 32; jl++) {
            float mine = hown[jl];
            float theirs = __shfl_xor_sync(0xffffffffu, mine, 1);
            h[jl]      = hf ? theirs : mine;
            h[32 + jl] = hf ? mine   : theirs;
        }
    }

    // ----- layer 3 (q-half): wf[24] = w[e][hf*24 .. hf*24+24) -----
    float wf[24];
    {
        u64 acc3[12];
        #pragma unroll
        for (int t = 0; t < 12; t++) acc3[t] = 0ull;
        #pragma unroll 4
        for (int j = 0; j < 64; j++) {
            u64 hj = pk2(h[j], h[j]);
            #pragma unroll
            for (int qi = 0; qi < 6; qi++) {
                ulonglong2 wp = w3p[j * 12 + hf * 6 + qi];
                acc3[2 * qi + 0] = ffma2(hj, wp.x, acc3[2 * qi + 0]);
                acc3[2 * qi + 1] = ffma2(hj, wp.y, acc3[2 * qi + 1]);
            }
        }
        #pragma unroll
        for (int qi = 0; qi < 6; qi++) {
            float p0, p1, p2, p3;
            up2(acc3[2 * qi + 0], p0, p1);
            up2(acc3[2 * qi + 1], p2, p3);
            wf[qi * 4 + 0] = p0 * 0.125f;
            wf[qi * 4 + 1] = p1 * 0.125f;
            wf[qi * 4 + 2] = p2 * 0.125f;
            wf[qi * 4 + 3] = p3 * 0.125f;
        }
    }

    // w1/w2 regions dead from here; fbuf aliases pool[0..4608)
    __syncthreads();
    float* fbufw = pool + wid * 1152;       // 32 rows x 36 floats (16B-aligned)

    // ----- f9 and Sv (duplicated per pair) -----
    float f9[9];
    #pragma unroll
    for (int b = 0; b < 9; b++)
        f9[b] = valid ? __ldg(&fsph[(size_t)ec * 9 + b]) : 0.0f;

    float Sv[81];
    #pragma unroll
    for (int a = 0; a < 9; a++) {
        float s0x = 0.f, s0y = 0.f, s0z = 0.f, s0w = 0.f;
        float s1x = 0.f, s1y = 0.f, s1z = 0.f, s1w = 0.f;
        float s2 = 0.f;
        #pragma unroll
        for (int b = 0; b < 9; b++) {
            float fb = f9[b];
            const float4* tp = (const float4*)&Tsh[(a * 9 + b) * 12];
            float4 t0 = tp[0];
            float4 t1 = tp[1];
            float  t2 = Tsh[(a * 9 + b) * 12 + 8];
            s0x += fb * t0.x; s0y += fb * t0.y; s0z += fb * t0.z; s0w += fb * t0.w;
            s1x += fb * t1.x; s1y += fb * t1.y; s1z += fb * t1.z; s1w += fb * t1.w;
            s2  += fb * t2;
        }
        Sv[a * 9 + 0] = s0x; Sv[a * 9 + 1] = s0y; Sv[a * 9 + 2] = s0z; Sv[a * 9 + 3] = s0w;
        Sv[a * 9 + 4] = s1x; Sv[a * 9 + 5] = s1y; Sv[a * 9 + 6] = s1z; Sv[a * 9 + 7] = s1w;
        Sv[a * 9 + 8] = s2;
    }

    const float4* xq4 = (const float4*)(x + (size_t)src * 144);
    float4* fb = (float4*)(fbufw + lane * 36);

    // ----- message: 2 rounds; this thread's chunk c = hf*2 + r -----
    #pragma unroll 1
    for (int r = 0; r < 2; r++) {
        int c = hf * 2 + r;

        float xf[36];
        if (valid) {
            #pragma unroll
            for (int q = 0; q < 9; q++) {
                float4 v = __ldg(&xq4[c * 9 + q]);
                xf[q * 4 + 0] = v.x; xf[q * 4 + 1] = v.y;
                xf[q * 4 + 2] = v.z; xf[q * 4 + 3] = v.w;
            }
        } else {
            #pragma unroll
            for (int q = 0; q < 36; q++) xf[q] = 0.f;
        }

        // compute + stage this chunk's 36 outputs
        #pragma unroll
        for (int q = 0; q < 9; q++) {
            float rr[4];
            #pragma unroll
            for (int i = 0; i < 4; i++) {
                const int cf = q * 4 + i;
                const int mm = cf / 9;
                const int d  = cf % 9;
                float s = 0.f;
                #pragma unroll
                for (int a = 0; a < 9; a++) s += xf[mm * 9 + a] * Sv[a * 9 + d];
                float fac = wf[r * 12 + mm * 3 + 0] * awsh[d]
                          + wf[r * 12 + mm * 3 + 1] * awsh[9 + d]
                          + wf[r * 12 + mm * 3 + 2] * awsh[18 + d];
                rr[i] = s * fac;
            }
            fb[q] = make_float4(rr[0], rr[1], rr[2], rr[3]);
        }
        __syncwarp();

        // cooperative flush: 4 groups of 8 rows; 4 lanes contiguous per row
        #pragma unroll
        for (int g = 0; g < 4; g++) {
            int owner = 8 * g + (lane >> 2);
            int dste  = __shfl_sync(0xffffffffu, dst, owner);
            int ve    = __shfl_sync(0xffffffffu, valid, owner);
            int co    = ((owner & 1) * 2 + r) * 36;     // owner's chunk offset
            const float4* sb = (const float4*)(fbufw + owner * 36);
            float* ob = out + (size_t)dste * 144 + co;
            #pragma unroll
            for (int r4 = 0; r4 < 2; r4++) {
                int q = r4 * 4 + (lane & 3);
                float4 v = sb[q];
                if (ve)
                    asm volatile("red.global.add.v4.f32 [%0], {%1, %2, %3, %4};"
                                 :: "l"(ob + q * 4),
                                    "f"(v.x), "f"(v.y), "f"(v.z), "f"(v.w)
                                 : "memory");
            }
            if ((lane & 3) == 0) {
                float4 v = sb[8];
                if (ve)
                    asm volatile("red.global.add.v4.f32 [%0], {%1, %2, %3, %4};"
                                 :: "l"(ob + 32),
                                    "f"(v.x), "f"(v.y), "f"(v.z), "f"(v.w)
                                 : "memory");
            }
        }
        __syncwarp();
    }
}

// ---------------------------------------------------------------------------
// kernel_launch
// inputs: 0:x 1:filter_sph 2:weight_in 3:edge_idx 4:Ux_re 5:Ux_im 6:Uf_re
//         7:Uf_im 8:Vout_re 9:Vout_im 10:W1 11:W2 12:W3 13:a_w 14:denominator
// ---------------------------------------------------------------------------
extern "C" void kernel_launch(void* const* d_in, const int* in_sizes, int n_in,
                              void* d_out, int out_size) {
    const float* x    = (const float*)d_in[0];
    const float* fsph = (const float*)d_in[1];
    const float* win  = (const float*)d_in[2];
    const int*   eidx = (const int*)  d_in[3];
    const float* Uxr  = (const float*)d_in[4];
    const float* Uxi  = (const float*)d_in[5];
    const float* Ufr  = (const float*)d_in[6];
    const float* Ufi  = (const float*)d_in[7];
    const float* Vr   = (const float*)d_in[8];
    const float* Vi   = (const float*)d_in[9];
    const float* W1   = (const float*)d_in[10];
    const float* W2   = (const float*)d_in[11];
    const float* W3   = (const float*)d_in[12];
    const float* aw   = (const float*)d_in[13];
    const float* den  = (const float*)d_in[14];
    float* out = (float*)d_out;

    int E = in_sizes[1] / 9;      // filter_sph is [E, 9]
    int n4 = out_size / 4;

    kprep<<<(n4 + 255) / 256, 256>>>(Uxr, Uxi, Ufr, Ufi, Vr, Vi, den,
                                     (float4*)out, n4);
    kedge<<<(E + 63) / 64, 128>>>(win, fsph, eidx, W1, W2, W3, aw, x, out, E);
}

// round 10
// speedup vs baseline: 1.3049x; 1.3049x over previous
#include <cuda_runtime.h>

// Problem constants (fixed shapes for this problem)
#define NEDGE 160000

// Scratch (static device arrays — cudaMalloc is forbidden)
__device__ __align__(16) float g_T[972];   // T[(a*9+b)*12 + d], pad 12

typedef unsigned long long u64;

// ---------------------------------------------------------------------------
// packed f32x2 helpers (Blackwell FFMA2)
// ---------------------------------------------------------------------------
__device__ __forceinline__ u64 pk2(float x, float y) {
    u64 r; asm("mov.b64 %0, {%1, %2};" : "=l"(r) : "f"(x), "f"(y)); return r;
}
__device__ __forceinline__ void up2(u64 v, float& x, float& y) {
    asm("mov.b64 {%0, %1}, %2;" : "=f"(x), "=f"(y) : "l"(v));
}
__device__ __forceinline__ u64 ffma2(u64 a, u64 b, u64 c) {
    u64 d; asm("fma.rn.f32x2 %0, %1, %2, %3;" : "=l"(d) : "l"(a), "l"(b), "l"(c));
    return d;
}

__device__ __forceinline__ float sspf(float x) {
    float e = __expf(-fabsf(x));
    return fmaxf(x, 0.0f) + __logf(1.0f + e) - 0.69314718055994531f;
}

// ---------------------------------------------------------------------------
// gridval: real 9x9 grid value of one spherical basis vector through
// pad -> ifftshift -> truncate -> irfft2 (numpy Im(DC)-dropped convention)
// ---------------------------------------------------------------------------
__device__ __forceinline__ float gridval(const float* __restrict__ Ur,
                                         const float* __restrict__ Ui,
                                         int a, int s, int t,
                                         const float* C, const float* S) {
    float acc = 0.0f;
    #pragma unroll
    for (int v = 0; v < 5; v++) {
        float gr = 0.0f, gi = 0.0f;
        int jj = (v + 4) % 9 - 2;                 // padded col -> U col
        if (jj >= 0 && jj < 5) {
            #pragma unroll
            for (int u = 0; u < 9; u++) {
                int ii = (u + 4) % 9 - 2;         // padded row -> U row
                if (ii >= 0 && ii < 5) {
                    float cr = Ur[a * 25 + ii * 5 + jj];
                    float ci = Ui[a * 25 + ii * 5 + jj];
                    int k = (u * s) % 9;
                    gr += cr * C[k] - ci * S[k];
                    gi += cr * S[k] + ci * C[k];
                }
            }
        }
        if (v == 0) {
            acc += gr;                             // Im(DC) dropped
        } else {
            int k2 = (v * t) % 9;
            acc += 2.0f * (gr * C[k2] - gi * S[k2]);
        }
    }
    return acc * (1.0f / 81.0f);
}

// ---------------------------------------------------------------------------
// kprep: all blocks zero the output; block 0 additionally builds T.
// ---------------------------------------------------------------------------
__global__ void __launch_bounds__(256) kprep(
    const float* __restrict__ Uxr, const float* __restrict__ Uxi,
    const float* __restrict__ Ufr, const float* __restrict__ Ufi,
    const float* __restrict__ Vr,  const float* __restrict__ Vi,
    const float* __restrict__ denom,
    float4* __restrict__ o4, int n4) {
    __shared__ float C9[9], S9[9];
    __shared__ float Gx[729], Gf[729], Pm[729];

    int tid = threadIdx.x;
    int i = blockIdx.x * 256 + tid;
    if (i < n4) o4[i] = make_float4(0.f, 0.f, 0.f, 0.f);

    if (blockIdx.x != 0) return;

    if (tid < 9) {
        double ang = 2.0 * 3.14159265358979323846 * (double)tid / 9.0;
        C9[tid] = (float)cos(ang);
        S9[tid] = (float)sin(ang);
    }
    __syncthreads();
    for (int idx = tid; idx < 729; idx += 256) {
        {   // grid bases: idx = a*81 + s*9 + t
            int a = idx / 81, s = (idx / 9) % 9, t = idx % 9;
            Gx[idx] = gridval(Uxr, Uxi, a, s, t, C9, S9);
            Gf[idx] = gridval(Ufr, Ufi, a, s, t, C9, S9);
        }
        {   // projection: idx = (s*9+t)*9 + d
            int st = idx / 9, d = idx % 9;
            int s = st / 9, t = st % 9;
            float p = 0.0f;
            #pragma unroll
            for (int u = 0; u < 9; u++)
                #pragma unroll
                for (int k = 0; k < 5; k++) {
                    int th = (u * s + k * t) % 9;
                    p += Vr[u * 45 + k * 9 + d] * C9[th]
                       + Vi[u * 45 + k * 9 + d] * S9[th];
                }
            Pm[idx] = p;
        }
    }
    __syncthreads();
    float inv = 1.0f / denom[0];
    for (int idx = tid; idx < 729; idx += 256) {
        int a = idx / 81, b = (idx / 9) % 9, d = idx % 9;
        float acc = 0.0f;
        #pragma unroll 9
        for (int st = 0; st < 81; st++)
            acc += Gx[a * 81 + st] * Gf[b * 81 + st] * Pm[st * 9 + d];
        g_T[(a * 9 + b) * 12 + d] = acc * inv;
    }
}

// ---------------------------------------------------------------------------
// kfuse: thread-per-edge MLP + message + scatter, one kernel, no pairing.
//   Phase 1: R7 MLP (packed FFMA2, weights in smem pool).
//   Bridge:  acc3 -> wst (smem, stride 49 floats: 17*l mod 32, conflict-free
//            scalar access; aliases the dead weight pool after a barrier).
//   Phase 2: R7 message per chunk (Sv in regs, aligned cooperative atomic
//            flush via per-warp fbuf aliased after the pool).
// ---------------------------------------------------------------------------
__global__ void __launch_bounds__(128, 3) kfuse(
    const float* __restrict__ win,
    const float* __restrict__ fsph,
    const int*   __restrict__ eidx,
    const float* __restrict__ W1,
    const float* __restrict__ W2,
    const float* __restrict__ W3,
    const float* __restrict__ aw,
    const float* __restrict__ x,
    float* __restrict__ out,
    int E) {
    // pool: [weights 7680] during MLP; [wst 6272 | fbuf 4608] during message
    __shared__ __align__(16) float pool[10880];
    __shared__ __align__(16) float Tsh[972];
    __shared__ float awsh[27];

    float4* w1s = (float4*)pool;            // 8x64    (512 floats)
    float4* w2s = (float4*)(pool + 512);    // 64x64   (4096 floats)
    float4* w3s = (float4*)(pool + 4608);   // 64x48   (3072 floats)

    int tid  = threadIdx.x;
    int wid  = tid >> 5;
    int lane = tid & 31;

    // ---- stage weights / T / aw ----
    const float4* W1v = (const float4*)W1;
    const float4* W2v = (const float4*)W2;
    const float4* W3v = (const float4*)W3;
    w1s[tid] = W1v[tid];
    #pragma unroll
    for (int i = 0; i < 8; i++) w2s[tid + i * 128] = W2v[tid + i * 128];
    #pragma unroll
    for (int i = 0; i < 6; i++) w3s[tid + i * 128] = W3v[tid + i * 128];
    #pragma unroll
    for (int i = 0; i < 8; i++) {
        int idx = tid + i * 128;
        if (idx < 972) Tsh[idx] = g_T[idx];
    }
    if (tid < 27) awsh[tid] = aw[tid];
    __syncthreads();

    int e = blockIdx.x * 128 + tid;
    int valid = (e < E) ? 1 : 0;
    int ec = valid ? e : 0;
    int dst = __ldg(&eidx[ec]);
    int src = __ldg(&eidx[E + ec]);

    const ulonglong2* w1p = (const ulonglong2*)w1s;
    const ulonglong2* w2p = (const ulonglong2*)w2s;
    const ulonglong2* w3p = (const ulonglong2*)w3s;

    float4 wa = __ldg(&((const float4*)win)[(size_t)ec * 2 + 0]);
    float4 wb = __ldg(&((const float4*)win)[(size_t)ec * 2 + 1]);
    float wi[8] = {wa.x, wa.y, wa.z, wa.w, wb.x, wb.y, wb.z, wb.w};

    u64 acc[32];
    float h[64];

    // ----- layer 1: h = ssp((win @ W1) / sqrt(8)) -----
    #pragma unroll
    for (int t = 0; t < 32; t++) acc[t] = 0ull;
    #pragma unroll
    for (int i = 0; i < 8; i++) {
        u64 hi = pk2(wi[i], wi[i]);
        #pragma unroll
        for (int kq = 0; kq < 16; kq++) {
            ulonglong2 wp = w1p[i * 16 + kq];
            acc[2 * kq + 0] = ffma2(hi, wp.x, acc[2 * kq + 0]);
            acc[2 * kq + 1] = ffma2(hi, wp.y, acc[2 * kq + 1]);
        }
    }
    const float s1 = 0.35355339059327373f;
    #pragma unroll
    for (int t = 0; t < 32; t++) {
        float v0, v1; up2(acc[t], v0, v1);
        h[2 * t + 0] = sspf(v0 * s1);
        h[2 * t + 1] = sspf(v1 * s1);
    }

    // ----- layer 2: h = ssp((h @ W2) * 0.125) -----
    #pragma unroll
    for (int t = 0; t < 32; t++) acc[t] = 0ull;
    #pragma unroll 4
    for (int j = 0; j < 64; j++) {
        u64 hj = pk2(h[j], h[j]);
        #pragma unroll
        for (int kq = 0; kq < 16; kq++) {
            ulonglong2 wp = w2p[j * 16 + kq];
            acc[2 * kq + 0] = ffma2(hj, wp.x, acc[2 * kq + 0]);
            acc[2 * kq + 1] = ffma2(hj, wp.y, acc[2 * kq + 1]);
        }
    }
    #pragma unroll
    for (int t = 0; t < 32; t++) {
        float v0, v1; up2(acc[t], v0, v1);
        h[2 * t + 0] = sspf(v0 * 0.125f);
        h[2 * t + 1] = sspf(v1 * 0.125f);
    }

    // ----- layer 3: w = (h @ W3) * 0.125 -----
    u64 acc3[24];
    #pragma unroll
    for (int t = 0; t < 24; t++) acc3[t] = 0ull;
    #pragma unroll 4
    for (int j = 0; j < 64; j++) {
        u64 hj = pk2(h[j], h[j]);
        #pragma unroll
        for (int q = 0; q < 12; q++) {
            ulonglong2 wp = w3p[j * 12 + q];
            acc3[2 * q + 0] = ffma2(hj, wp.x, acc3[2 * q + 0]);
            acc3[2 * q + 1] = ffma2(hj, wp.y, acc3[2 * q + 1]);
        }
    }

    // ----- bridge: park w[48] in smem (weights dead after this barrier) -----
    __syncthreads();
    float* wst = pool + tid * 49;           // stride 49: conflict-free scalar
    #pragma unroll
    for (int q = 0; q < 12; q++) {
        float p0, p1, p2, p3;
        up2(acc3[2 * q + 0], p0, p1);
        up2(acc3[2 * q + 1], p2, p3);
        wst[4 * q + 0] = p0 * 0.125f;
        wst[4 * q + 1] = p1 * 0.125f;
        wst[4 * q + 2] = p2 * 0.125f;
        wst[4 * q + 3] = p3 * 0.125f;
    }

    // ----- f9 and Sv -----
    float f9[9];
    #pragma unroll
    for (int b = 0; b < 9; b++)
        f9[b] = valid ? __ldg(&fsph[(size_t)ec * 9 + b]) : 0.0f;

    float Sv[81];
    #pragma unroll
    for (int a = 0; a < 9; a++) {
        float s0x = 0.f, s0y = 0.f, s0z = 0.f, s0w = 0.f;
        float s1x = 0.f, s1y = 0.f, s1z = 0.f, s1w = 0.f;
        float s2 = 0.f;
        #pragma unroll
        for (int b = 0; b < 9; b++) {
            float fb = f9[b];
            const float4* tp = (const float4*)&Tsh[(a * 9 + b) * 12];
            float4 t0 = tp[0];
            float4 t1 = tp[1];
            float  t2 = Tsh[(a * 9 + b) * 12 + 8];
            s0x += fb * t0.x; s0y += fb * t0.y; s0z += fb * t0.z; s0w += fb * t0.w;
            s1x += fb * t1.x; s1y += fb * t1.y; s1z += fb * t1.z; s1w += fb * t1.w;
            s2  += fb * t2;
        }
        Sv[a * 9 + 0] = s0x; Sv[a * 9 + 1] = s0y; Sv[a * 9 + 2] = s0z; Sv[a * 9 + 3] = s0w;
        Sv[a * 9 + 4] = s1x; Sv[a * 9 + 5] = s1y; Sv[a * 9 + 6] = s1z; Sv[a * 9 + 7] = s1w;
        Sv[a * 9 + 8] = s2;
    }

    const float4* xq4 = (const float4*)(x + (size_t)src * 144);
    float* fbufw = pool + 6272 + wid * 1152;            // 32 rows x 36 floats
    float4* fb = (float4*)(fbufw + lane * 36);          // 16B-aligned

    // ----- message: 4 chunks of 4 muls (36 floats each) -----
    #pragma unroll 1
    for (int c = 0; c < 4; c++) {
        float xf[36];
        if (valid) {
            #pragma unroll
            for (int q = 0; q < 9; q++) {
                float4 v = __ldg(&xq4[c * 9 + q]);
                xf[q * 4 + 0] = v.x; xf[q * 4 + 1] = v.y;
                xf[q * 4 + 2] = v.z; xf[q * 4 + 3] = v.w;
            }
        } else {
            #pragma unroll
            for (int q = 0; q < 36; q++) xf[q] = 0.f;
        }
        float wf[12];
        #pragma unroll
        for (int k = 0; k < 12; k++) wf[k] = wst[c * 12 + k];

        // compute + stage this chunk's 36 outputs
        #pragma unroll
        for (int q = 0; q < 9; q++) {
            float r[4];
            #pragma unroll
            for (int i = 0; i < 4; i++) {
                const int cf = q * 4 + i;
                const int mm = cf / 9;
                const int d  = cf % 9;
                float s = 0.f;
                #pragma unroll
                for (int a = 0; a < 9; a++) s += xf[mm * 9 + a] * Sv[a * 9 + d];
                float fac = wf[mm * 3 + 0] * awsh[d]
                          + wf[mm * 3 + 1] * awsh[9 + d]
                          + wf[mm * 3 + 2] * awsh[18 + d];
                r[i] = s * fac;
            }
            fb[q] = make_float4(r[0], r[1], r[2], r[3]);
        }
        __syncwarp();

        // cooperative flush: 4 groups of 8 edges; 4 lanes contiguous per edge
        #pragma unroll
        for (int g = 0; g < 4; g++) {
            int owner = 8 * g + (lane >> 2);
            int dste  = __shfl_sync(0xffffffffu, dst, owner);
            int ve    = __shfl_sync(0xffffffffu, valid, owner);
            const float4* sb = (const float4*)(fbufw + owner * 36);
            float* ob = out + (size_t)dste * 144 + c * 36;
            #pragma unroll
            for (int r4 = 0; r4 < 2; r4++) {
                int q = r4 * 4 + (lane & 3);
                float4 v = sb[q];
                if (ve)
                    asm volatile("red.global.add.v4.f32 [%0], {%1, %2, %3, %4};"
                                 :: "l"(ob + q * 4),
                                    "f"(v.x), "f"(v.y), "f"(v.z), "f"(v.w)
                                 : "memory");
            }
            if ((lane & 3) == 0) {
                float4 v = sb[8];
                if (ve)
                    asm volatile("red.global.add.v4.f32 [%0], {%1, %2, %3, %4};"
                                 :: "l"(ob + 32),
                                    "f"(v.x), "f"(v.y), "f"(v.z), "f"(v.w)
                                 : "memory");
            }
        }
        __syncwarp();
    }
}

// ---------------------------------------------------------------------------
// kernel_launch
// inputs: 0:x 1:filter_sph 2:weight_in 3:edge_idx 4:Ux_re 5:Ux_im 6:Uf_re
//         7:Uf_im 8:Vout_re 9:Vout_im 10:W1 11:W2 12:W3 13:a_w 14:denominator
// ---------------------------------------------------------------------------
extern "C" void kernel_launch(void* const* d_in, const int* in_sizes, int n_in,
                              void* d_out, int out_size) {
    const float* x    = (const float*)d_in[0];
    const float* fsph = (const float*)d_in[1];
    const float* win  = (const float*)d_in[2];
    const int*   eidx = (const int*)  d_in[3];
    const float* Uxr  = (const float*)d_in[4];
    const float* Uxi  = (const float*)d_in[5];
    const float* Ufr  = (const float*)d_in[6];
    const float* Ufi  = (const float*)d_in[7];
    const float* Vr   = (const float*)d_in[8];
    const float* Vi   = (const float*)d_in[9];
    const float* W1   = (const float*)d_in[10];
    const float* W2   = (const float*)d_in[11];
    const float* W3   = (const float*)d_in[12];
    const float* aw   = (const float*)d_in[13];
    const float* den  = (const float*)d_in[14];
    float* out = (float*)d_out;

    int E = in_sizes[1] / 9;      // filter_sph is [E, 9]
    int n4 = out_size / 4;

    kprep<<<(n4 + 255) / 256, 256>>>(Uxr, Uxi, Ufr, Ufi, Vr, Vi, den,
                                     (float4*)out, n4);
    kfuse<<<(E + 127) / 128, 128>>>(win, fsph, eidx, W1, W2, W3, aw, x, out, E);
}